// round 1
// baseline (speedup 1.0000x reference)
#include <cuda_runtime.h>
#include <cstdint>

// Problem constants
static constexpr int Bb = 2, Ss = 2048, Hh = 16, DH = 64, Dd = 1024;
static constexpr int Mrows = Bb * Ss;           // 4096

// Scratch (static device globals — no allocations allowed)
__device__ float g_qkv[4096 * 3072];            // x @ w_qkv
__device__ float g_q[Bb * Hh * Ss * DH];        // rope'd, scaled, tf32-rounded
__device__ float g_k[Bb * Hh * Ss * DH];
__device__ float g_v[Bb * Hh * Ss * DH];
__device__ float g_ao[4096 * 1024];             // attention output [B*S, H*DH]

__device__ __forceinline__ uint32_t f2tf(float f) {
    uint32_t u;
    asm("cvt.rna.tf32.f32 %0, %1;" : "=r"(u) : "f"(f));
    return u;
}

__device__ __forceinline__ void mma8(float (&c)[4], const uint32_t (&a)[4],
                                     uint32_t b0, uint32_t b1) {
    asm volatile(
        "mma.sync.aligned.m16n8k8.row.col.f32.tf32.tf32.f32 "
        "{%0,%1,%2,%3}, {%4,%5,%6,%7}, {%8,%9}, {%0,%1,%2,%3};"
        : "+f"(c[0]), "+f"(c[1]), "+f"(c[2]), "+f"(c[3])
        : "r"(a[0]), "r"(a[1]), "r"(a[2]), "r"(a[3]), "r"(b0), "r"(b1));
}

// ---------------------------------------------------------------------------
// tf32 GEMM: C[M,N] = A[M,K] @ B[K,N], all row-major fp32 in/out.
// Block 128x128, BK=16, 256 threads, 8 warps as 2x4 of 64x32 warp tiles.
// ---------------------------------------------------------------------------
__global__ __launch_bounds__(256) void gemm_tf32(
    const float* __restrict__ A, const float* __restrict__ Bm,
    float* __restrict__ C, int M, int N, int K) {
    __shared__ uint32_t As[128][20];   // [m][k], pad 20 -> conflict-free A frags
    __shared__ uint32_t Bs[16][136];   // [k][n], pad 136 -> conflict-free B frags

    const int tid = threadIdx.x, lane = tid & 31, warp = tid >> 5;
    const int wm = (warp >> 2) * 64, wn = (warp & 3) * 32;
    const int lr = lane >> 2, lq = lane & 3;
    const int bm = blockIdx.y * 128, bn = blockIdx.x * 128;

    const int ar = tid >> 2, ac = (tid & 3) << 2;    // A loader: 64 rows x 16 cols
    const int br = tid >> 5, bc = (tid & 31) << 2;   // B loader: 8 rows x 128 cols

    float acc[4][4][4];
#pragma unroll
    for (int mt = 0; mt < 4; mt++)
#pragma unroll
        for (int nt = 0; nt < 4; nt++)
#pragma unroll
            for (int i = 0; i < 4; i++) acc[mt][nt][i] = 0.f;

    for (int kt = 0; kt < K; kt += 16) {
#pragma unroll
        for (int i = 0; i < 2; i++) {
            float4 va = *(const float4*)&A[(size_t)(bm + ar + 64 * i) * K + kt + ac];
            uint4 ua = make_uint4(f2tf(va.x), f2tf(va.y), f2tf(va.z), f2tf(va.w));
            *(uint4*)&As[ar + 64 * i][ac] = ua;
            float4 vb = *(const float4*)&Bm[(size_t)(kt + br + 8 * i) * N + bn + bc];
            uint4 ub = make_uint4(f2tf(vb.x), f2tf(vb.y), f2tf(vb.z), f2tf(vb.w));
            *(uint4*)&Bs[br + 8 * i][bc] = ub;
        }
        __syncthreads();

#pragma unroll
        for (int ks = 0; ks < 16; ks += 8) {
            uint32_t a[4][4], b[4][2];
#pragma unroll
            for (int mt = 0; mt < 4; mt++) {
                int r0 = wm + mt * 16 + lr, c0 = ks + lq;
                a[mt][0] = As[r0][c0];
                a[mt][1] = As[r0 + 8][c0];
                a[mt][2] = As[r0][c0 + 4];
                a[mt][3] = As[r0 + 8][c0 + 4];
            }
#pragma unroll
            for (int nt = 0; nt < 4; nt++) {
                int cc = wn + nt * 8 + lr, kr = ks + lq;
                b[nt][0] = Bs[kr][cc];
                b[nt][1] = Bs[kr + 4][cc];
            }
#pragma unroll
            for (int mt = 0; mt < 4; mt++)
#pragma unroll
                for (int nt = 0; nt < 4; nt++)
                    mma8(acc[mt][nt], a[mt], b[nt][0], b[nt][1]);
        }
        __syncthreads();
    }

#pragma unroll
    for (int mt = 0; mt < 4; mt++)
#pragma unroll
        for (int nt = 0; nt < 4; nt++) {
            int row = bm + wm + mt * 16 + lr;
            int col = bn + wn + nt * 8 + (lq << 1);
            *(float2*)&C[(size_t)row * N + col] =
                make_float2(acc[mt][nt][0], acc[mt][nt][1]);
            *(float2*)&C[(size_t)(row + 8) * N + col] =
                make_float2(acc[mt][nt][2], acc[mt][nt][3]);
        }
}

// ---------------------------------------------------------------------------
// RoPE + head transpose + tf32 pre-rounding (+ fold score scale into Q).
// One thread per (b, s, h, d<32) pair — handles (d, d+32) for q, k, v.
// ---------------------------------------------------------------------------
__global__ __launch_bounds__(256) void rope_kernel(
    const float* __restrict__ qkv, const float* __restrict__ freqs,
    float* __restrict__ Qo, float* __restrict__ Ko, float* __restrict__ Vo) {
    int idx = blockIdx.x * 256 + threadIdx.x;   // 0 .. 2*2048*16*32-1
    int d = idx & 31;
    int h = (idx >> 5) & 15;
    int s = (idx >> 9) & 2047;
    int b = idx >> 20;

    const float* base = qkv + (size_t)(b * Ss + s) * 3072 + h * 64 + d;
    float q1 = base[0], q2 = base[32];
    float k1 = base[1024], k2 = base[1024 + 32];
    float v1 = base[2048], v2 = base[2048 + 32];

    float f1 = freqs[s * 64 + d], f2 = freqs[s * 64 + d + 32];
    float c1, s1, c2, s2;
    sincosf(f1, &s1, &c1);
    sincosf(f2, &s2, &c2);

    const float scale = 0.125f;   // 1/sqrt(64), folded into Q
    float qo1 = (q1 * c1 - q2 * s1) * scale;
    float qo2 = (q2 * c2 + q1 * s2) * scale;
    float ko1 = k1 * c1 - k2 * s1;
    float ko2 = k2 * c2 + k1 * s2;

    size_t ob = ((size_t)(b * Hh + h) * Ss + s) * 64 + d;
    Qo[ob]      = __uint_as_float(f2tf(qo1));
    Qo[ob + 32] = __uint_as_float(f2tf(qo2));
    Ko[ob]      = __uint_as_float(f2tf(ko1));
    Ko[ob + 32] = __uint_as_float(f2tf(ko2));
    Vo[ob]      = __uint_as_float(f2tf(v1));
    Vo[ob + 32] = __uint_as_float(f2tf(v2));
}

// ---------------------------------------------------------------------------
// Causal flash attention, tf32 mma. Br=128 (8 warps x 16 rows), Bc=64.
// Q fragments register-resident; K^T and V in smem (pad 72 -> conflict-free).
// V rows permuted [0,4,1,5,2,6,3,7] per 8-group so score C-fragments feed
// directly as P A-fragments (no cross-lane shuffles).
// Output written to AO[B*S, H*DH] (pre-transposed for the out projection).
// ---------------------------------------------------------------------------
__global__ __launch_bounds__(256) void attn_kernel(
    const float* __restrict__ Q, const float* __restrict__ Kt,
    const float* __restrict__ V, float* __restrict__ AO) {
    const int qt = blockIdx.x;                 // q tile of 128 rows
    const int h = blockIdx.y, b = blockIdx.z;
    const int tid = threadIdx.x, lane = tid & 31, warp = tid >> 5;
    const int lr = lane >> 2, lq = lane & 3;
    const int q0 = qt * 128;

    __shared__ uint32_t Ks[64][72];   // [d][kv]  (K^T)
    __shared__ uint32_t Vs[64][72];   // [kv slot][d]

    const size_t bh = (size_t)(b * Hh + h) * Ss;
    const float* Qg = Q + (bh + q0) * 64;
    const uint32_t* Kg = (const uint32_t*)(Kt + bh * 64);
    const uint32_t* Vg = (const uint32_t*)(V + bh * 64);

    // Q fragments: 16 rows per warp x 64 k  -> 8 k-tiles x 4 regs
    uint32_t qf[8][4];
    {
        int r0 = warp * 16 + lr;
#pragma unroll
        for (int k8 = 0; k8 < 8; k8++) {
            int c = k8 * 8 + lq;
            qf[k8][0] = __float_as_uint(Qg[r0 * 64 + c]);
            qf[k8][1] = __float_as_uint(Qg[(r0 + 8) * 64 + c]);
            qf[k8][2] = __float_as_uint(Qg[r0 * 64 + c + 4]);
            qf[k8][3] = __float_as_uint(Qg[(r0 + 8) * 64 + c + 4]);
        }
    }

    float o[8][4];
#pragma unroll
    for (int dn = 0; dn < 8; dn++)
#pragma unroll
        for (int i = 0; i < 4; i++) o[dn][i] = 0.f;
    float m0 = -1e30f, m1 = -1e30f, l0 = 0.f, l1 = 0.f;

    // Tile loader mapping: 256 threads cover 64x64, 16 elems each.
    const int kv = tid >> 2;
    const int dbase = (tid & 3) << 4;
    const int kvg = kv & 7;
    const int slot = (kv & ~7) | ((kvg & 1) ? ((kvg >> 1) + 4) : (kvg >> 1));

    const int jmax = 2 * qt + 1;
    for (int jt = 0; jt <= jmax; jt++) {
        // ---- load K tile (transposed) and V tile (row-permuted) ----
        const uint32_t* kp = Kg + (size_t)(jt * 64 + kv) * 64 + dbase;
#pragma unroll
        for (int u = 0; u < 4; u++) {
            uint4 w = *(const uint4*)(kp + u * 4);
            Ks[dbase + u * 4 + 0][kv] = w.x;
            Ks[dbase + u * 4 + 1][kv] = w.y;
            Ks[dbase + u * 4 + 2][kv] = w.z;
            Ks[dbase + u * 4 + 3][kv] = w.w;
        }
        const uint32_t* vp = Vg + (size_t)(jt * 64 + kv) * 64 + dbase;
#pragma unroll
        for (int u = 0; u < 4; u++)
            *(uint4*)&Vs[slot][dbase + u * 4] = *(const uint4*)(vp + u * 4);
        __syncthreads();

        // ---- scores: S = Q @ K^T (scale pre-folded into Q) ----
        float sc[8][4];
#pragma unroll
        for (int nt = 0; nt < 8; nt++)
#pragma unroll
            for (int i = 0; i < 4; i++) sc[nt][i] = 0.f;
#pragma unroll
        for (int k8 = 0; k8 < 8; k8++)
#pragma unroll
            for (int nt = 0; nt < 8; nt++)
                mma8(sc[nt], qf[k8],
                     Ks[k8 * 8 + lq][nt * 8 + lr],
                     Ks[k8 * 8 + lq + 4][nt * 8 + lr]);

        // ---- causal mask (only tiles that can cross the diagonal) ----
        if (jt >= 2 * qt) {
            int r1 = q0 + warp * 16 + lr;
#pragma unroll
            for (int nt = 0; nt < 8; nt++) {
                int key = jt * 64 + nt * 8 + (lq << 1);
                if (key > r1) sc[nt][0] = -1e30f;
                if (key + 1 > r1) sc[nt][1] = -1e30f;
                if (key > r1 + 8) sc[nt][2] = -1e30f;
                if (key + 1 > r1 + 8) sc[nt][3] = -1e30f;
            }
        }

        // ---- online softmax ----
        float mx0 = -1e30f, mx1 = -1e30f;
#pragma unroll
        for (int nt = 0; nt < 8; nt++) {
            mx0 = fmaxf(mx0, fmaxf(sc[nt][0], sc[nt][1]));
            mx1 = fmaxf(mx1, fmaxf(sc[nt][2], sc[nt][3]));
        }
        mx0 = fmaxf(mx0, __shfl_xor_sync(0xffffffffu, mx0, 1));
        mx0 = fmaxf(mx0, __shfl_xor_sync(0xffffffffu, mx0, 2));
        mx1 = fmaxf(mx1, __shfl_xor_sync(0xffffffffu, mx1, 1));
        mx1 = fmaxf(mx1, __shfl_xor_sync(0xffffffffu, mx1, 2));
        float mn0 = fmaxf(m0, mx0), mn1 = fmaxf(m1, mx1);
        float fac0 = __expf(m0 - mn0), fac1 = __expf(m1 - mn1);

        float s0 = 0.f, s1 = 0.f;
#pragma unroll
        for (int nt = 0; nt < 8; nt++) {
            float p0 = __expf(sc[nt][0] - mn0);
            float p1 = __expf(sc[nt][1] - mn0);
            float p2 = __expf(sc[nt][2] - mn1);
            float p3 = __expf(sc[nt][3] - mn1);
            s0 += p0 + p1;
            s1 += p2 + p3;
            sc[nt][0] = __uint_as_float(f2tf(p0));
            sc[nt][1] = __uint_as_float(f2tf(p1));
            sc[nt][2] = __uint_as_float(f2tf(p2));
            sc[nt][3] = __uint_as_float(f2tf(p3));
        }
        s0 += __shfl_xor_sync(0xffffffffu, s0, 1);
        s0 += __shfl_xor_sync(0xffffffffu, s0, 2);
        s1 += __shfl_xor_sync(0xffffffffu, s1, 1);
        s1 += __shfl_xor_sync(0xffffffffu, s1, 2);
        l0 = l0 * fac0 + s0;
        l1 = l1 * fac1 + s1;
        m0 = mn0;
        m1 = mn1;
#pragma unroll
        for (int dn = 0; dn < 8; dn++) {
            o[dn][0] *= fac0; o[dn][1] *= fac0;
            o[dn][2] *= fac1; o[dn][3] *= fac1;
        }

        // ---- O += P @ V (C-frag -> A-frag via V row permutation) ----
#pragma unroll
        for (int k8 = 0; k8 < 8; k8++) {
            uint32_t af[4] = {__float_as_uint(sc[k8][0]), __float_as_uint(sc[k8][2]),
                              __float_as_uint(sc[k8][1]), __float_as_uint(sc[k8][3])};
#pragma unroll
            for (int dn = 0; dn < 8; dn++)
                mma8(o[dn], af,
                     Vs[k8 * 8 + lq][dn * 8 + lr],
                     Vs[k8 * 8 + lq + 4][dn * 8 + lr]);
        }
        __syncthreads();
    }

    // ---- epilogue: normalize, write AO[b*S + s, h*64 + d] ----
    float i0 = 1.0f / l0, i1 = 1.0f / l1;
    int grow = b * Ss + q0 + warp * 16 + lr;
    float* op0 = AO + (size_t)grow * Dd + h * 64;
    float* op1 = AO + (size_t)(grow + 8) * Dd + h * 64;
#pragma unroll
    for (int dn = 0; dn < 8; dn++) {
        int c = dn * 8 + (lq << 1);
        *(float2*)&op0[c] = make_float2(o[dn][0] * i0, o[dn][1] * i0);
        *(float2*)&op1[c] = make_float2(o[dn][2] * i1, o[dn][3] * i1);
    }
}

// ---------------------------------------------------------------------------
extern "C" void kernel_launch(void* const* d_in, const int* in_sizes, int n_in,
                              void* d_out, int out_size) {
    const float* x = (const float*)d_in[0];       // [2, 2048, 1024]
    const float* w_qkv = (const float*)d_in[1];   // [1024, 3072]
    const float* w_out = (const float*)d_in[2];   // [1024, 1024]
    const float* freqs = (const float*)d_in[3];   // [2048, 64]
    float* out = (float*)d_out;                   // [2, 2048, 1024]

    float *qkv, *q, *k, *v, *ao;
    cudaGetSymbolAddress((void**)&qkv, g_qkv);
    cudaGetSymbolAddress((void**)&q, g_q);
    cudaGetSymbolAddress((void**)&k, g_k);
    cudaGetSymbolAddress((void**)&v, g_v);
    cudaGetSymbolAddress((void**)&ao, g_ao);

    // 1) QKV projection: [4096,1024] @ [1024,3072]
    gemm_tf32<<<dim3(3072 / 128, Mrows / 128), 256>>>(x, w_qkv, qkv, Mrows, 3072, Dd);
    // 2) RoPE + transpose + tf32 round (+ fold 1/sqrt(dh) into Q)
    rope_kernel<<<(Bb * Ss * Hh * 32) / 256, 256>>>(qkv, freqs, q, k, v);
    // 3) Causal flash attention
    attn_kernel<<<dim3(Ss / 128, Hh, Bb), 256>>>(q, k, v, ao);
    // 4) Output projection: [4096,1024] @ [1024,1024]
    gemm_tf32<<<dim3(Dd / 128, Mrows / 128), 256>>>(ao, w_out, out, Mrows, Dd, Dd);
}

// round 3
// speedup vs baseline: 1.1563x; 1.1563x over previous
#include <cuda_runtime.h>
#include <cstdint>

// Problem constants
static constexpr int Bb = 2, Ss = 2048, Hh = 16, DH = 64, Dd = 1024;
static constexpr int Mrows = Bb * Ss;           // 4096

// Scratch (static device globals — no allocations allowed)
__device__ float g_qkv[4096 * 3072];            // x @ w_qkv
__device__ float g_q[Bb * Hh * Ss * DH];        // rope'd, scaled(*log2e), tf32-rounded
__device__ float g_k[Bb * Hh * Ss * DH];
__device__ float g_v[Bb * Hh * Ss * DH];
__device__ float g_ao[4096 * 1024];             // attention output [B*S, H*DH]

__device__ __forceinline__ uint32_t f2tf(float f) {
    uint32_t u;
    asm("cvt.rna.tf32.f32 %0, %1;" : "=r"(u) : "f"(f));
    return u;
}

__device__ __forceinline__ float ex2(float x) {
    float y;
    asm("ex2.approx.f32 %0, %1;" : "=f"(y) : "f"(x));
    return y;
}

__device__ __forceinline__ void cp16(uint32_t smem_addr, const void* gptr) {
    asm volatile("cp.async.ca.shared.global [%0], [%1], 16;"
                 :: "r"(smem_addr), "l"(gptr));
}

__device__ __forceinline__ void mma8(float (&c)[4], const uint32_t (&a)[4],
                                     uint32_t b0, uint32_t b1) {
    asm volatile(
        "mma.sync.aligned.m16n8k8.row.col.f32.tf32.tf32.f32 "
        "{%0,%1,%2,%3}, {%4,%5,%6,%7}, {%8,%9}, {%0,%1,%2,%3};"
        : "+f"(c[0]), "+f"(c[1]), "+f"(c[2]), "+f"(c[3])
        : "r"(a[0]), "r"(a[1]), "r"(a[2]), "r"(a[3]), "r"(b0), "r"(b1));
}

// ---------------------------------------------------------------------------
// tf32 GEMM: C[M,N] = A[M,K] @ B[K,N], all row-major fp32 in/out.
// Block 128x128, BK=16, 256 threads, 8 warps as 2x4 of 64x32 warp tiles.
// (unchanged — known good)
// ---------------------------------------------------------------------------
__global__ __launch_bounds__(256) void gemm_tf32(
    const float* __restrict__ A, const float* __restrict__ Bm,
    float* __restrict__ C, int M, int N, int K) {
    __shared__ uint32_t As[128][20];   // [m][k], pad 20 -> conflict-free A frags
    __shared__ uint32_t Bs[16][136];   // [k][n], pad 136 -> conflict-free B frags

    const int tid = threadIdx.x, lane = tid & 31, warp = tid >> 5;
    const int wm = (warp >> 2) * 64, wn = (warp & 3) * 32;
    const int lr = lane >> 2, lq = lane & 3;
    const int bm = blockIdx.y * 128, bn = blockIdx.x * 128;

    const int ar = tid >> 2, ac = (tid & 3) << 2;    // A loader: 64 rows x 16 cols
    const int br = tid >> 5, bc = (tid & 31) << 2;   // B loader: 8 rows x 128 cols

    float acc[4][4][4];
#pragma unroll
    for (int mt = 0; mt < 4; mt++)
#pragma unroll
        for (int nt = 0; nt < 4; nt++)
#pragma unroll
            for (int i = 0; i < 4; i++) acc[mt][nt][i] = 0.f;

    for (int kt = 0; kt < K; kt += 16) {
#pragma unroll
        for (int i = 0; i < 2; i++) {
            float4 va = *(const float4*)&A[(size_t)(bm + ar + 64 * i) * K + kt + ac];
            uint4 ua = make_uint4(f2tf(va.x), f2tf(va.y), f2tf(va.z), f2tf(va.w));
            *(uint4*)&As[ar + 64 * i][ac] = ua;
            float4 vb = *(const float4*)&Bm[(size_t)(kt + br + 8 * i) * N + bn + bc];
            uint4 ub = make_uint4(f2tf(vb.x), f2tf(vb.y), f2tf(vb.z), f2tf(vb.w));
            *(uint4*)&Bs[br + 8 * i][bc] = ub;
        }
        __syncthreads();

#pragma unroll
        for (int ks = 0; ks < 16; ks += 8) {
            uint32_t a[4][4], b[4][2];
#pragma unroll
            for (int mt = 0; mt < 4; mt++) {
                int r0 = wm + mt * 16 + lr, c0 = ks + lq;
                a[mt][0] = As[r0][c0];
                a[mt][1] = As[r0 + 8][c0];
                a[mt][2] = As[r0][c0 + 4];
                a[mt][3] = As[r0 + 8][c0 + 4];
            }
#pragma unroll
            for (int nt = 0; nt < 4; nt++) {
                int cc = wn + nt * 8 + lr, kr = ks + lq;
                b[nt][0] = Bs[kr][cc];
                b[nt][1] = Bs[kr + 4][cc];
            }
#pragma unroll
            for (int mt = 0; mt < 4; mt++)
#pragma unroll
                for (int nt = 0; nt < 4; nt++)
                    mma8(acc[mt][nt], a[mt], b[nt][0], b[nt][1]);
        }
        __syncthreads();
    }

#pragma unroll
    for (int mt = 0; mt < 4; mt++)
#pragma unroll
        for (int nt = 0; nt < 4; nt++) {
            int row = bm + wm + mt * 16 + lr;
            int col = bn + wn + nt * 8 + (lq << 1);
            *(float2*)&C[(size_t)row * N + col] =
                make_float2(acc[mt][nt][0], acc[mt][nt][1]);
            *(float2*)&C[(size_t)(row + 8) * N + col] =
                make_float2(acc[mt][nt][2], acc[mt][nt][3]);
        }
}

// ---------------------------------------------------------------------------
// RoPE + head transpose + tf32 pre-rounding.
// Q gets scale = 1/sqrt(dh) * log2(e) folded in (softmax uses ex2 directly).
// ---------------------------------------------------------------------------
__global__ __launch_bounds__(256) void rope_kernel(
    const float* __restrict__ qkv, const float* __restrict__ freqs,
    float* __restrict__ Qo, float* __restrict__ Ko, float* __restrict__ Vo) {
    int idx = blockIdx.x * 256 + threadIdx.x;   // 0 .. 2*2048*16*32-1
    int d = idx & 31;
    int h = (idx >> 5) & 15;
    int s = (idx >> 9) & 2047;
    int b = idx >> 20;

    const float* base = qkv + (size_t)(b * Ss + s) * 3072 + h * 64 + d;
    float q1 = base[0], q2 = base[32];
    float k1 = base[1024], k2 = base[1024 + 32];
    float v1 = base[2048], v2 = base[2048 + 32];

    float f1 = freqs[s * 64 + d], f2 = freqs[s * 64 + d + 32];
    float c1, s1, c2, s2;
    sincosf(f1, &s1, &c1);
    sincosf(f2, &s2, &c2);

    const float scale = 0.125f * 1.4426950408889634f;  // 1/sqrt(64) * log2(e)
    float qo1 = (q1 * c1 - q2 * s1) * scale;
    float qo2 = (q2 * c2 + q1 * s2) * scale;
    float ko1 = k1 * c1 - k2 * s1;
    float ko2 = k2 * c2 + k1 * s2;

    size_t ob = ((size_t)(b * Hh + h) * Ss + s) * 64 + d;
    Qo[ob]      = __uint_as_float(f2tf(qo1));
    Qo[ob + 32] = __uint_as_float(f2tf(qo2));
    Ko[ob]      = __uint_as_float(f2tf(ko1));
    Ko[ob + 32] = __uint_as_float(f2tf(ko2));
    Vo[ob]      = __uint_as_float(f2tf(v1));
    Vo[ob + 32] = __uint_as_float(f2tf(v2));
}

// ---------------------------------------------------------------------------
// Causal flash attention, tf32 mma. Br=128 (8 warps x 16 rows), Bc=64.
// K stored row-major [kv][d] pad-68 (bank = 4*lr+lq, bijective -> conflict-free),
// V row-permuted [0,4,1,5,2,6,3,7] pad-72 (bank = 8*lq+lr, bijective).
// K/V staged via cp.async, 2-deep double buffering (dynamic smem, 70 KB).
// q-tiles scheduled biggest-first (reversed blockIdx).
// ---------------------------------------------------------------------------
static constexpr int KS_WORDS = 64 * 68;        // one K buffer
static constexpr int VS_WORDS = 64 * 72;        // one V buffer
static constexpr int ATTN_SMEM_BYTES = (2 * KS_WORDS + 2 * VS_WORDS) * 4;  // 71680

__global__ __launch_bounds__(256) void attn_kernel(
    const float* __restrict__ Q, const float* __restrict__ K,
    const float* __restrict__ V, float* __restrict__ AO) {
    extern __shared__ uint32_t dynsmem[];
    uint32_t (*Ks)[64][68] = reinterpret_cast<uint32_t (*)[64][68]>(dynsmem);
    uint32_t (*Vs)[64][72] =
        reinterpret_cast<uint32_t (*)[64][72]>(dynsmem + 2 * KS_WORDS);

    const int qt = gridDim.x - 1 - blockIdx.x;   // reversed: heavy blocks first
    const int h = blockIdx.y, b = blockIdx.z;
    const int tid = threadIdx.x, lane = tid & 31, warp = tid >> 5;
    const int lr = lane >> 2, lq = lane & 3;
    const int q0 = qt * 128;

    const size_t bh = (size_t)(b * Hh + h) * Ss;
    const float* Qg = Q + (bh + q0) * 64;
    const float* Kg = K + bh * 64;
    const float* Vg = V + bh * 64;

    // Q fragments: 16 rows per warp x 64 k -> 8 k-tiles x 4 regs
    uint32_t qf[8][4];
    {
        int r0 = warp * 16 + lr;
#pragma unroll
        for (int k8 = 0; k8 < 8; k8++) {
            int c = k8 * 8 + lq;
            qf[k8][0] = __float_as_uint(Qg[r0 * 64 + c]);
            qf[k8][1] = __float_as_uint(Qg[(r0 + 8) * 64 + c]);
            qf[k8][2] = __float_as_uint(Qg[r0 * 64 + c + 4]);
            qf[k8][3] = __float_as_uint(Qg[(r0 + 8) * 64 + c + 4]);
        }
    }

    float o[8][4];
#pragma unroll
    for (int dn = 0; dn < 8; dn++)
#pragma unroll
        for (int i = 0; i < 4; i++) o[dn][i] = 0.f;
    float m0 = -1e30f, m1 = -1e30f, l0 = 0.f, l1 = 0.f;

    // cp.async loader: 256 threads x 4 chunks of 16B cover each 64x64 tile.
    const int lrow = tid >> 4;          // 0..15
    const int lcol = (tid & 15) << 2;   // 0,4,...,60

    auto issue_tile = [&](int jt, int buf) {
        const float* kb = Kg + (size_t)(jt * 64) * 64;
        const float* vb = Vg + (size_t)(jt * 64) * 64;
#pragma unroll
        for (int u = 0; u < 4; u++) {
            int r = lrow + 16 * u;
            cp16((uint32_t)__cvta_generic_to_shared(&Ks[buf][r][lcol]),
                 kb + r * 64 + lcol);
            int g = r & 7;
            int slot = (r & ~7) | ((g & 1) ? ((g >> 1) + 4) : (g >> 1));
            cp16((uint32_t)__cvta_generic_to_shared(&Vs[buf][slot][lcol]),
                 vb + r * 64 + lcol);
        }
        asm volatile("cp.async.commit_group;");
    };

    const int jmax = 2 * qt + 1;
    issue_tile(0, 0);

    for (int jt = 0; jt <= jmax; jt++) {
        const int cur = jt & 1;
        if (jt < jmax) {
            issue_tile(jt + 1, cur ^ 1);
            asm volatile("cp.async.wait_group 1;");
        } else {
            asm volatile("cp.async.wait_group 0;");
        }
        __syncthreads();

        // ---- scores: S = Q @ K^T (scale*log2e pre-folded into Q) ----
        float sc[8][4];
#pragma unroll
        for (int nt = 0; nt < 8; nt++)
#pragma unroll
            for (int i = 0; i < 4; i++) sc[nt][i] = 0.f;
#pragma unroll
        for (int k8 = 0; k8 < 8; k8++)
#pragma unroll
            for (int nt = 0; nt < 8; nt++)
                mma8(sc[nt], qf[k8],
                     Ks[cur][nt * 8 + lr][k8 * 8 + lq],
                     Ks[cur][nt * 8 + lr][k8 * 8 + lq + 4]);

        // ---- causal mask (only tiles that can cross the diagonal) ----
        if (jt >= 2 * qt) {
            int r1 = q0 + warp * 16 + lr;
#pragma unroll
            for (int nt = 0; nt < 8; nt++) {
                int key = jt * 64 + nt * 8 + (lq << 1);
                if (key > r1) sc[nt][0] = -1e30f;
                if (key + 1 > r1) sc[nt][1] = -1e30f;
                if (key > r1 + 8) sc[nt][2] = -1e30f;
                if (key + 1 > r1 + 8) sc[nt][3] = -1e30f;
            }
        }

        // ---- online softmax (log2 domain -> ex2) ----
        float mx0 = -1e30f, mx1 = -1e30f;
#pragma unroll
        for (int nt = 0; nt < 8; nt++) {
            mx0 = fmaxf(mx0, fmaxf(sc[nt][0], sc[nt][1]));
            mx1 = fmaxf(mx1, fmaxf(sc[nt][2], sc[nt][3]));
        }
        mx0 = fmaxf(mx0, __shfl_xor_sync(0xffffffffu, mx0, 1));
        mx0 = fmaxf(mx0, __shfl_xor_sync(0xffffffffu, mx0, 2));
        mx1 = fmaxf(mx1, __shfl_xor_sync(0xffffffffu, mx1, 1));
        mx1 = fmaxf(mx1, __shfl_xor_sync(0xffffffffu, mx1, 2));
        float mn0 = fmaxf(m0, mx0), mn1 = fmaxf(m1, mx1);
        float fac0 = ex2(m0 - mn0), fac1 = ex2(m1 - mn1);

        float s0 = 0.f, s1 = 0.f;
#pragma unroll
        for (int nt = 0; nt < 8; nt++) {
            float p0 = ex2(sc[nt][0] - mn0);
            float p1 = ex2(sc[nt][1] - mn0);
            float p2 = ex2(sc[nt][2] - mn1);
            float p3 = ex2(sc[nt][3] - mn1);
            s0 += p0 + p1;
            s1 += p2 + p3;
            sc[nt][0] = __uint_as_float(f2tf(p0));
            sc[nt][1] = __uint_as_float(f2tf(p1));
            sc[nt][2] = __uint_as_float(f2tf(p2));
            sc[nt][3] = __uint_as_float(f2tf(p3));
        }
        s0 += __shfl_xor_sync(0xffffffffu, s0, 1);
        s0 += __shfl_xor_sync(0xffffffffu, s0, 2);
        s1 += __shfl_xor_sync(0xffffffffu, s1, 1);
        s1 += __shfl_xor_sync(0xffffffffu, s1, 2);
        l0 = l0 * fac0 + s0;
        l1 = l1 * fac1 + s1;
        m0 = mn0;
        m1 = mn1;
#pragma unroll
        for (int dn = 0; dn < 8; dn++) {
            o[dn][0] *= fac0; o[dn][1] *= fac0;
            o[dn][2] *= fac1; o[dn][3] *= fac1;
        }

        // ---- O += P @ V (C-frag -> A-frag via V row permutation) ----
#pragma unroll
        for (int k8 = 0; k8 < 8; k8++) {
            uint32_t af[4] = {__float_as_uint(sc[k8][0]), __float_as_uint(sc[k8][2]),
                              __float_as_uint(sc[k8][1]), __float_as_uint(sc[k8][3])};
#pragma unroll
            for (int dn = 0; dn < 8; dn++)
                mma8(o[dn], af,
                     Vs[cur][k8 * 8 + lq][dn * 8 + lr],
                     Vs[cur][k8 * 8 + lq + 4][dn * 8 + lr]);
        }
        __syncthreads();
    }

    // ---- epilogue: normalize, write AO[b*S + s, h*64 + d] ----
    float i0 = 1.0f / l0, i1 = 1.0f / l1;
    int grow = b * Ss + q0 + warp * 16 + lr;
    float* op0 = AO + (size_t)grow * Dd + h * 64;
    float* op1 = AO + (size_t)(grow + 8) * Dd + h * 64;
#pragma unroll
    for (int dn = 0; dn < 8; dn++) {
        int c = dn * 8 + (lq << 1);
        *(float2*)&op0[c] = make_float2(o[dn][0] * i0, o[dn][1] * i0);
        *(float2*)&op1[c] = make_float2(o[dn][2] * i1, o[dn][3] * i1);
    }
}

// ---------------------------------------------------------------------------
extern "C" void kernel_launch(void* const* d_in, const int* in_sizes, int n_in,
                              void* d_out, int out_size) {
    const float* x = (const float*)d_in[0];       // [2, 2048, 1024]
    const float* w_qkv = (const float*)d_in[1];   // [1024, 3072]
    const float* w_out = (const float*)d_in[2];   // [1024, 1024]
    const float* freqs = (const float*)d_in[3];   // [2048, 64]
    float* out = (float*)d_out;                   // [2, 2048, 1024]

    float *qkv, *q, *k, *v, *ao;
    cudaGetSymbolAddress((void**)&qkv, g_qkv);
    cudaGetSymbolAddress((void**)&q, g_q);
    cudaGetSymbolAddress((void**)&k, g_k);
    cudaGetSymbolAddress((void**)&v, g_v);
    cudaGetSymbolAddress((void**)&ao, g_ao);

    // Opt in to >48KB dynamic smem for the attention kernel (idempotent).
    cudaFuncSetAttribute(attn_kernel,
                         cudaFuncAttributeMaxDynamicSharedMemorySize,
                         ATTN_SMEM_BYTES);

    // 1) QKV projection: [4096,1024] @ [1024,3072]
    gemm_tf32<<<dim3(3072 / 128, Mrows / 128), 256>>>(x, w_qkv, qkv, Mrows, 3072, Dd);
    // 2) RoPE + transpose + tf32 round (+ fold scale*log2e into Q)
    rope_kernel<<<(Bb * Ss * Hh * 32) / 256, 256>>>(qkv, freqs, q, k, v);
    // 3) Causal flash attention
    attn_kernel<<<dim3(Ss / 128, Hh, Bb), 256, ATTN_SMEM_BYTES>>>(q, k, v, ao);
    // 4) Output projection: [4096,1024] @ [1024,1024]
    gemm_tf32<<<dim3(Dd / 128, Mrows / 128), 256>>>(ao, w_out, out, Mrows, Dd, Dd);
}

// round 4
// speedup vs baseline: 1.2112x; 1.0475x over previous
#include <cuda_runtime.h>
#include <cstdint>

// Problem constants
static constexpr int Bb = 2, Ss = 2048, Hh = 16, DH = 64, Dd = 1024;
static constexpr int Mrows = Bb * Ss;           // 4096

// Scratch (static device globals — no allocations allowed)
__device__ float g_qkv[4096 * 3072];            // x @ w_qkv
__device__ float g_q[Bb * Hh * Ss * DH];        // rope'd, scaled(*log2e), tf32-rounded
__device__ float g_k[Bb * Hh * Ss * DH];
__device__ float g_v[Bb * Hh * Ss * DH];
__device__ float g_ao[4096 * 1024];             // attention output [B*S, H*DH]

__device__ __forceinline__ uint32_t f2tf(float f) {
    uint32_t u;
    asm("cvt.rna.tf32.f32 %0, %1;" : "=r"(u) : "f"(f));
    return u;
}

__device__ __forceinline__ float ex2(float x) {
    float y;
    asm("ex2.approx.f32 %0, %1;" : "=f"(y) : "f"(x));
    return y;
}

__device__ __forceinline__ void cp16(void* smem_ptr, const void* gptr) {
    uint32_t sa = (uint32_t)__cvta_generic_to_shared(smem_ptr);
    asm volatile("cp.async.ca.shared.global [%0], [%1], 16;"
                 :: "r"(sa), "l"(gptr));
}

__device__ __forceinline__ void mma8(float (&c)[4], const uint32_t (&a)[4],
                                     uint32_t b0, uint32_t b1) {
    asm volatile(
        "mma.sync.aligned.m16n8k8.row.col.f32.tf32.tf32.f32 "
        "{%0,%1,%2,%3}, {%4,%5,%6,%7}, {%8,%9}, {%0,%1,%2,%3};"
        : "+f"(c[0]), "+f"(c[1]), "+f"(c[2]), "+f"(c[3])
        : "r"(a[0]), "r"(a[1]), "r"(a[2]), "r"(a[3]), "r"(b0), "r"(b1));
}

// ---------------------------------------------------------------------------
// tf32 GEMM v2: C[M,N] = A[M,K] @ B[K,N], row-major fp32.
// Block 128x128, BK=16, 256 threads, 8 warps as 2x4 of 64x32 warp tiles.
// 3-stage cp.async pipeline (raw fp32 in smem, tf32 cvt at fragment load),
// ONE __syncthreads per k-step.
// ---------------------------------------------------------------------------
static constexpr int AS_F = 128 * 20;           // floats per A stage
static constexpr int BS_F = 16 * 136;           // floats per B stage
static constexpr int GEMM_SMEM = 3 * (AS_F + BS_F) * 4;   // 56832 bytes

__global__ __launch_bounds__(256) void gemm_tf32(
    const float* __restrict__ A, const float* __restrict__ Bm,
    float* __restrict__ C, int M, int N, int K) {
    extern __shared__ float gsm[];
    float (*As)[128][20] = reinterpret_cast<float (*)[128][20]>(gsm);
    float (*Bs)[16][136] = reinterpret_cast<float (*)[16][136]>(gsm + 3 * AS_F);

    const int tid = threadIdx.x, lane = tid & 31, warp = tid >> 5;
    const int wm = (warp >> 2) * 64, wn = (warp & 3) * 32;
    const int lr = lane >> 2, lq = lane & 3;
    const int bm = blockIdx.y * 128, bn = blockIdx.x * 128;

    const int ar = tid >> 2, ac = (tid & 3) << 2;    // A loader: 64 rows x 16 cols
    const int br = tid >> 5, bc = (tid & 31) << 2;   // B loader: 8 rows x 128 cols

    auto issue = [&](int i, int buf) {
        int kt = i * 16;
#pragma unroll
        for (int half = 0; half < 2; half++) {
            cp16(&As[buf][ar + 64 * half][ac],
                 &A[(size_t)(bm + ar + 64 * half) * K + kt + ac]);
            cp16(&Bs[buf][br + 8 * half][bc],
                 &Bm[(size_t)(kt + br + 8 * half) * N + bn + bc]);
        }
        asm volatile("cp.async.commit_group;");
    };

    float acc[4][4][4];
#pragma unroll
    for (int mt = 0; mt < 4; mt++)
#pragma unroll
        for (int nt = 0; nt < 4; nt++)
#pragma unroll
            for (int i = 0; i < 4; i++) acc[mt][nt][i] = 0.f;

    const int niter = K / 16;
    issue(0, 0);
    if (niter > 1) issue(1, 1);

    for (int i = 0; i < niter; i++) {
        const int buf = i % 3;
        if (i < niter - 1)
            asm volatile("cp.async.wait_group 1;");
        else
            asm volatile("cp.async.wait_group 0;");
        __syncthreads();
        if (i + 2 < niter) issue(i + 2, (i + 2) % 3);

#pragma unroll
        for (int ks = 0; ks < 16; ks += 8) {
            uint32_t a[4][4], b[4][2];
#pragma unroll
            for (int mt = 0; mt < 4; mt++) {
                int r0 = wm + mt * 16 + lr, c0 = ks + lq;
                a[mt][0] = f2tf(As[buf][r0][c0]);
                a[mt][1] = f2tf(As[buf][r0 + 8][c0]);
                a[mt][2] = f2tf(As[buf][r0][c0 + 4]);
                a[mt][3] = f2tf(As[buf][r0 + 8][c0 + 4]);
            }
#pragma unroll
            for (int nt = 0; nt < 4; nt++) {
                int cc = wn + nt * 8 + lr, kr = ks + lq;
                b[nt][0] = f2tf(Bs[buf][kr][cc]);
                b[nt][1] = f2tf(Bs[buf][kr + 4][cc]);
            }
#pragma unroll
            for (int mt = 0; mt < 4; mt++)
#pragma unroll
                for (int nt = 0; nt < 4; nt++)
                    mma8(acc[mt][nt], a[mt], b[nt][0], b[nt][1]);
        }
    }

#pragma unroll
    for (int mt = 0; mt < 4; mt++)
#pragma unroll
        for (int nt = 0; nt < 4; nt++) {
            int row = bm + wm + mt * 16 + lr;
            int col = bn + wn + nt * 8 + (lq << 1);
            *(float2*)&C[(size_t)row * N + col] =
                make_float2(acc[mt][nt][0], acc[mt][nt][1]);
            *(float2*)&C[(size_t)(row + 8) * N + col] =
                make_float2(acc[mt][nt][2], acc[mt][nt][3]);
        }
}

// ---------------------------------------------------------------------------
// RoPE v2: one thread per (b, s, d<32), looping over all 16 heads.
// sincos computed ONCE per (s,d) pair per thread (262K total, was 8.4M).
// Q gets scale = 1/sqrt(dh) * log2(e) folded in (softmax uses ex2 directly).
// ---------------------------------------------------------------------------
__global__ __launch_bounds__(256) void rope_kernel(
    const float* __restrict__ qkv, const float* __restrict__ freqs,
    float* __restrict__ Qo, float* __restrict__ Ko, float* __restrict__ Vo) {
    int idx = blockIdx.x * 256 + threadIdx.x;   // 0 .. 2*2048*32-1
    int d = idx & 31;
    int bs = idx >> 5;            // b*2048 + s
    int s = bs & 2047;

    float f1 = freqs[s * 64 + d], f2 = freqs[s * 64 + d + 32];
    float c1, s1, c2, s2;
    sincosf(f1, &s1, &c1);
    sincosf(f2, &s2, &c2);

    const float scale = 0.125f * 1.4426950408889634f;  // 1/sqrt(64) * log2(e)
    const float* base0 = qkv + (size_t)bs * 3072 + d;
    int b = bs >> 11;

#pragma unroll 4
    for (int h = 0; h < Hh; h++) {
        const float* base = base0 + h * 64;
        float q1 = base[0], q2 = base[32];
        float k1 = base[1024], k2 = base[1024 + 32];
        float v1 = base[2048], v2 = base[2048 + 32];

        float qo1 = (q1 * c1 - q2 * s1) * scale;
        float qo2 = (q2 * c2 + q1 * s2) * scale;
        float ko1 = k1 * c1 - k2 * s1;
        float ko2 = k2 * c2 + k1 * s2;

        size_t ob = ((size_t)(b * Hh + h) * Ss + s) * 64 + d;
        Qo[ob]      = __uint_as_float(f2tf(qo1));
        Qo[ob + 32] = __uint_as_float(f2tf(qo2));
        Ko[ob]      = __uint_as_float(f2tf(ko1));
        Ko[ob + 32] = __uint_as_float(f2tf(ko2));
        Vo[ob]      = __uint_as_float(f2tf(v1));
        Vo[ob + 32] = __uint_as_float(f2tf(v2));
    }
}

// ---------------------------------------------------------------------------
// Causal flash attention, tf32 mma. Br=128 (8 warps x 16 rows), Bc=64.
// K stored row-major [kv][d] pad-68 (bank = 4*lr+lq, bijective -> conflict-free),
// V row-permuted [0,4,1,5,2,6,3,7] pad-72 (bank = 8*lq+lr, bijective).
// K/V staged via cp.async, 2-deep double buffering (dynamic smem, 70 KB).
// q-tiles scheduled biggest-first (reversed blockIdx). (unchanged from R3)
// ---------------------------------------------------------------------------
static constexpr int KS_WORDS = 64 * 68;        // one K buffer
static constexpr int VS_WORDS = 64 * 72;        // one V buffer
static constexpr int ATTN_SMEM_BYTES = (2 * KS_WORDS + 2 * VS_WORDS) * 4;  // 71680

__global__ __launch_bounds__(256) void attn_kernel(
    const float* __restrict__ Q, const float* __restrict__ K,
    const float* __restrict__ V, float* __restrict__ AO) {
    extern __shared__ uint32_t dynsmem[];
    uint32_t (*Ks)[64][68] = reinterpret_cast<uint32_t (*)[64][68]>(dynsmem);
    uint32_t (*Vs)[64][72] =
        reinterpret_cast<uint32_t (*)[64][72]>(dynsmem + 2 * KS_WORDS);

    const int qt = gridDim.x - 1 - blockIdx.x;   // reversed: heavy blocks first
    const int h = blockIdx.y, b = blockIdx.z;
    const int tid = threadIdx.x, lane = tid & 31, warp = tid >> 5;
    const int lr = lane >> 2, lq = lane & 3;
    const int q0 = qt * 128;

    const size_t bh = (size_t)(b * Hh + h) * Ss;
    const float* Qg = Q + (bh + q0) * 64;
    const float* Kg = K + bh * 64;
    const float* Vg = V + bh * 64;

    // Q fragments: 16 rows per warp x 64 k -> 8 k-tiles x 4 regs
    uint32_t qf[8][4];
    {
        int r0 = warp * 16 + lr;
#pragma unroll
        for (int k8 = 0; k8 < 8; k8++) {
            int c = k8 * 8 + lq;
            qf[k8][0] = __float_as_uint(Qg[r0 * 64 + c]);
            qf[k8][1] = __float_as_uint(Qg[(r0 + 8) * 64 + c]);
            qf[k8][2] = __float_as_uint(Qg[r0 * 64 + c + 4]);
            qf[k8][3] = __float_as_uint(Qg[(r0 + 8) * 64 + c + 4]);
        }
    }

    float o[8][4];
#pragma unroll
    for (int dn = 0; dn < 8; dn++)
#pragma unroll
        for (int i = 0; i < 4; i++) o[dn][i] = 0.f;
    float m0 = -1e30f, m1 = -1e30f, l0 = 0.f, l1 = 0.f;

    // cp.async loader: 256 threads x 4 chunks of 16B cover each 64x64 tile.
    const int lrow = tid >> 4;          // 0..15
    const int lcol = (tid & 15) << 2;   // 0,4,...,60

    auto issue_tile = [&](int jt, int buf) {
        const float* kb = Kg + (size_t)(jt * 64) * 64;
        const float* vb = Vg + (size_t)(jt * 64) * 64;
#pragma unroll
        for (int u = 0; u < 4; u++) {
            int r = lrow + 16 * u;
            cp16(&Ks[buf][r][lcol], kb + r * 64 + lcol);
            int g = r & 7;
            int slot = (r & ~7) | ((g & 1) ? ((g >> 1) + 4) : (g >> 1));
            cp16(&Vs[buf][slot][lcol], vb + r * 64 + lcol);
        }
        asm volatile("cp.async.commit_group;");
    };

    const int jmax = 2 * qt + 1;
    issue_tile(0, 0);

    for (int jt = 0; jt <= jmax; jt++) {
        const int cur = jt & 1;
        if (jt < jmax) {
            issue_tile(jt + 1, cur ^ 1);
            asm volatile("cp.async.wait_group 1;");
        } else {
            asm volatile("cp.async.wait_group 0;");
        }
        __syncthreads();

        // ---- scores: S = Q @ K^T (scale*log2e pre-folded into Q) ----
        float sc[8][4];
#pragma unroll
        for (int nt = 0; nt < 8; nt++)
#pragma unroll
            for (int i = 0; i < 4; i++) sc[nt][i] = 0.f;
#pragma unroll
        for (int k8 = 0; k8 < 8; k8++)
#pragma unroll
            for (int nt = 0; nt < 8; nt++)
                mma8(sc[nt], qf[k8],
                     Ks[cur][nt * 8 + lr][k8 * 8 + lq],
                     Ks[cur][nt * 8 + lr][k8 * 8 + lq + 4]);

        // ---- causal mask (only tiles that can cross the diagonal) ----
        if (jt >= 2 * qt) {
            int r1 = q0 + warp * 16 + lr;
#pragma unroll
            for (int nt = 0; nt < 8; nt++) {
                int key = jt * 64 + nt * 8 + (lq << 1);
                if (key > r1) sc[nt][0] = -1e30f;
                if (key + 1 > r1) sc[nt][1] = -1e30f;
                if (key > r1 + 8) sc[nt][2] = -1e30f;
                if (key + 1 > r1 + 8) sc[nt][3] = -1e30f;
            }
        }

        // ---- online softmax (log2 domain -> ex2) ----
        float mx0 = -1e30f, mx1 = -1e30f;
#pragma unroll
        for (int nt = 0; nt < 8; nt++) {
            mx0 = fmaxf(mx0, fmaxf(sc[nt][0], sc[nt][1]));
            mx1 = fmaxf(mx1, fmaxf(sc[nt][2], sc[nt][3]));
        }
        mx0 = fmaxf(mx0, __shfl_xor_sync(0xffffffffu, mx0, 1));
        mx0 = fmaxf(mx0, __shfl_xor_sync(0xffffffffu, mx0, 2));
        mx1 = fmaxf(mx1, __shfl_xor_sync(0xffffffffu, mx1, 1));
        mx1 = fmaxf(mx1, __shfl_xor_sync(0xffffffffu, mx1, 2));
        float mn0 = fmaxf(m0, mx0), mn1 = fmaxf(m1, mx1);
        float fac0 = ex2(m0 - mn0), fac1 = ex2(m1 - mn1);

        float s0 = 0.f, s1 = 0.f;
#pragma unroll
        for (int nt = 0; nt < 8; nt++) {
            float p0 = ex2(sc[nt][0] - mn0);
            float p1 = ex2(sc[nt][1] - mn0);
            float p2 = ex2(sc[nt][2] - mn1);
            float p3 = ex2(sc[nt][3] - mn1);
            s0 += p0 + p1;
            s1 += p2 + p3;
            sc[nt][0] = __uint_as_float(f2tf(p0));
            sc[nt][1] = __uint_as_float(f2tf(p1));
            sc[nt][2] = __uint_as_float(f2tf(p2));
            sc[nt][3] = __uint_as_float(f2tf(p3));
        }
        s0 += __shfl_xor_sync(0xffffffffu, s0, 1);
        s0 += __shfl_xor_sync(0xffffffffu, s0, 2);
        s1 += __shfl_xor_sync(0xffffffffu, s1, 1);
        s1 += __shfl_xor_sync(0xffffffffu, s1, 2);
        l0 = l0 * fac0 + s0;
        l1 = l1 * fac1 + s1;
        m0 = mn0;
        m1 = mn1;
#pragma unroll
        for (int dn = 0; dn < 8; dn++) {
            o[dn][0] *= fac0; o[dn][1] *= fac0;
            o[dn][2] *= fac1; o[dn][3] *= fac1;
        }

        // ---- O += P @ V (C-frag -> A-frag via V row permutation) ----
#pragma unroll
        for (int k8 = 0; k8 < 8; k8++) {
            uint32_t af[4] = {__float_as_uint(sc[k8][0]), __float_as_uint(sc[k8][2]),
                              __float_as_uint(sc[k8][1]), __float_as_uint(sc[k8][3])};
#pragma unroll
            for (int dn = 0; dn < 8; dn++)
                mma8(o[dn], af,
                     Vs[cur][k8 * 8 + lq][dn * 8 + lr],
                     Vs[cur][k8 * 8 + lq + 4][dn * 8 + lr]);
        }
        __syncthreads();
    }

    // ---- epilogue: normalize, write AO[b*S + s, h*64 + d] ----
    float i0 = 1.0f / l0, i1 = 1.0f / l1;
    int grow = b * Ss + q0 + warp * 16 + lr;
    float* op0 = AO + (size_t)grow * Dd + h * 64;
    float* op1 = AO + (size_t)(grow + 8) * Dd + h * 64;
#pragma unroll
    for (int dn = 0; dn < 8; dn++) {
        int c = dn * 8 + (lq << 1);
        *(float2*)&op0[c] = make_float2(o[dn][0] * i0, o[dn][1] * i0);
        *(float2*)&op1[c] = make_float2(o[dn][2] * i1, o[dn][3] * i1);
    }
}

// ---------------------------------------------------------------------------
extern "C" void kernel_launch(void* const* d_in, const int* in_sizes, int n_in,
                              void* d_out, int out_size) {
    const float* x = (const float*)d_in[0];       // [2, 2048, 1024]
    const float* w_qkv = (const float*)d_in[1];   // [1024, 3072]
    const float* w_out = (const float*)d_in[2];   // [1024, 1024]
    const float* freqs = (const float*)d_in[3];   // [2048, 64]
    float* out = (float*)d_out;                   // [2, 2048, 1024]

    float *qkv, *q, *k, *v, *ao;
    cudaGetSymbolAddress((void**)&qkv, g_qkv);
    cudaGetSymbolAddress((void**)&q, g_q);
    cudaGetSymbolAddress((void**)&k, g_k);
    cudaGetSymbolAddress((void**)&v, g_v);
    cudaGetSymbolAddress((void**)&ao, g_ao);

    // Opt in to >48KB dynamic smem (idempotent attribute sets).
    cudaFuncSetAttribute(attn_kernel,
                         cudaFuncAttributeMaxDynamicSharedMemorySize,
                         ATTN_SMEM_BYTES);
    cudaFuncSetAttribute(gemm_tf32,
                         cudaFuncAttributeMaxDynamicSharedMemorySize,
                         GEMM_SMEM);

    // 1) QKV projection: [4096,1024] @ [1024,3072]
    gemm_tf32<<<dim3(3072 / 128, Mrows / 128), 256, GEMM_SMEM>>>(
        x, w_qkv, qkv, Mrows, 3072, Dd);
    // 2) RoPE + transpose + tf32 round (+ fold scale*log2e into Q)
    rope_kernel<<<(Bb * Ss * 32) / 256, 256>>>(qkv, freqs, q, k, v);
    // 3) Causal flash attention
    attn_kernel<<<dim3(Ss / 128, Hh, Bb), 256, ATTN_SMEM_BYTES>>>(q, k, v, ao);
    // 4) Output projection: [4096,1024] @ [1024,1024]
    gemm_tf32<<<dim3(Dd / 128, Mrows / 128), 256, GEMM_SMEM>>>(
        ao, w_out, out, Mrows, Dd, Dd);
}